// round 13
// baseline (speedup 1.0000x reference)
#include <cuda_runtime.h>
#include <cuda_bf16.h>

#define B     16384
#define D     1024
#define N_PER 8
#define G     (B / N_PER)      // 2048
#define MARGIN 0.5f
#define N_PAIRS 28.0f          // 8*7/2

__device__ float g_group_loss[G];

// ===== Round-10 group kernel body, verbatim; only change: minBlocks=6 =====
__global__ __launch_bounds__(256, 6) void group_kernel(const float* __restrict__ emb) {
    const int g    = blockIdx.x;
    const int tid  = threadIdx.x;
    const int lane = tid & 31;
    const int warp = tid >> 5;

    const float4* base = reinterpret_cast<const float4*>(emb + (size_t)g * N_PER * D);
    float4 v[N_PER];
    float  sq[N_PER];

#pragma unroll
    for (int r = 0; r < N_PER; r++) {
        v[r] = base[r * (D / 4) + tid];
        sq[r] = v[r].x * v[r].x + v[r].y * v[r].y + v[r].z * v[r].z + v[r].w * v[r].w;
    }

#pragma unroll
    for (int r = 0; r < N_PER; r++) {
#pragma unroll
        for (int off = 16; off > 0; off >>= 1)
            sq[r] += __shfl_down_sync(0xFFFFFFFFu, sq[r], off);
    }

    __shared__ float s_sq[8][N_PER];
    if (lane == 0) {
#pragma unroll
        for (int r = 0; r < N_PER; r++) s_sq[warp][r] = sq[r];
    }
    __syncthreads();

    __shared__ float s_inv[N_PER];
    if (tid < N_PER) {
        float s = 0.0f;
#pragma unroll
        for (int w = 0; w < 8; w++) s += s_sq[w][tid];
        float nrm = fmaxf(sqrtf(s), 1e-12f);
        s_inv[tid] = 1.0f / nrm;
    }
    __syncthreads();

    float sx = 0.f, sy = 0.f, sz = 0.f, sw = 0.f;
#pragma unroll
    for (int r = 0; r < N_PER; r++) {
        const float inv = s_inv[r];
        sx += v[r].x * inv;
        sy += v[r].y * inv;
        sz += v[r].z * inv;
        sw += v[r].w * inv;
    }
    float part = sx * sx + sy * sy + sz * sz + sw * sw;

#pragma unroll
    for (int off = 16; off > 0; off >>= 1)
        part += __shfl_down_sync(0xFFFFFFFFu, part, off);

    __shared__ float s_part[8];
    if (lane == 0) s_part[warp] = part;
    __syncthreads();

    if (tid == 0) {
        float ss = 0.0f;
#pragma unroll
        for (int w = 0; w < 8; w++) ss += s_part[w];
        float mean_intra = 1.0f - (ss - (float)N_PER) / (2.0f * N_PAIRS);
        g_group_loss[g] = fmaxf(mean_intra - MARGIN, 0.0f);
        // PDL: signal dependent grid; its wait releases when all CTAs trigger.
        asm volatile("griddepcontrol.launch_dependents;" ::: "memory");
    }
}

// ===== Final reduction, PDL-gated (unchanged from round 10) =====
__global__ __launch_bounds__(512) void final_kernel(float* __restrict__ out) {
    asm volatile("griddepcontrol.wait;" ::: "memory");

    const int tid  = threadIdx.x;
    const int lane = tid & 31;
    const int warp = tid >> 5;

    float acc = 0.0f;
#pragma unroll
    for (int i = tid; i < G; i += 512) acc += __ldcg(&g_group_loss[i]);

#pragma unroll
    for (int off = 16; off > 0; off >>= 1)
        acc += __shfl_xor_sync(0xFFFFFFFFu, acc, off);

    __shared__ float s_part[16];
    if (lane == 0) s_part[warp] = acc;
    __syncthreads();

    if (tid == 0) {
        float s = 0.0f;
#pragma unroll
        for (int w = 0; w < 16; w++) s += s_part[w];
        out[0] = s / (float)G;
    }
}

extern "C" void kernel_launch(void* const* d_in, const int* in_sizes, int n_in,
                              void* d_out, int out_size) {
    const float* emb = (const float*)d_in[0];
    // d_in[1] = labels (arange(B)//8): grouping implicit in block->row mapping
    float* out = (float*)d_out;

    group_kernel<<<G, 256>>>(emb);

    cudaLaunchConfig_t cfg = {};
    cfg.gridDim  = dim3(1, 1, 1);
    cfg.blockDim = dim3(512, 1, 1);
    cfg.dynamicSmemBytes = 0;
    cfg.stream = 0;
    cudaLaunchAttribute attr[1];
    attr[0].id = cudaLaunchAttributeProgrammaticStreamSerialization;
    attr[0].val.programmaticStreamSerializationAllowed = 1;
    cfg.attrs = attr;
    cfg.numAttrs = 1;
    cudaLaunchKernelEx(&cfg, final_kernel, out);
}

// round 14
// speedup vs baseline: 1.0647x; 1.0647x over previous
#include <cuda_runtime.h>
#include <cuda_bf16.h>

#define B     16384
#define D     1024
#define N_PER 8
#define G     (B / N_PER)      // 2048
#define MARGIN 0.5f
#define N_PAIRS 28.0f          // 8*7/2

__device__ float g_group_loss[G];

// ===== Group kernel: round-10 structure, but data is READ TWICE instead of
// held in registers across the phase-1 barrier. Second read hits L2 (64 MB
// input < 126 MB L2; reread follows first touch within ~1k cycles).
// Register footprint drops -> more resident blocks -> higher DRAM duty. =====
__global__ __launch_bounds__(256) void group_kernel(const float* __restrict__ emb) {
    const int g    = blockIdx.x;
    const int tid  = threadIdx.x;
    const int lane = tid & 31;
    const int warp = tid >> 5;

    const float4* base = reinterpret_cast<const float4*>(emb + (size_t)g * N_PER * D);

    // ---- phase 1: per-row sum of squares (transient float4s only) ----
    float sq[N_PER];
#pragma unroll
    for (int r = 0; r < N_PER; r++) {
        float4 a = base[r * (D / 4) + tid];
        sq[r] = a.x * a.x + a.y * a.y + a.z * a.z + a.w * a.w;
    }

#pragma unroll
    for (int r = 0; r < N_PER; r++) {
#pragma unroll
        for (int off = 16; off > 0; off >>= 1)
            sq[r] += __shfl_down_sync(0xFFFFFFFFu, sq[r], off);
    }

    __shared__ float s_sq[8][N_PER];
    if (lane == 0) {
#pragma unroll
        for (int r = 0; r < N_PER; r++) s_sq[warp][r] = sq[r];
    }
    __syncthreads();

    __shared__ float s_inv[N_PER];
    if (tid < N_PER) {
        float s = 0.0f;
#pragma unroll
        for (int w = 0; w < 8; w++) s += s_sq[w][tid];
        float nrm = fmaxf(sqrtf(s), 1e-12f);
        s_inv[tid] = 1.0f / nrm;
    }
    __syncthreads();

    // ---- phase 2: reread tile (L2-hot), weighted group-sum + ||s||^2 ----
    float sx = 0.f, sy = 0.f, sz = 0.f, sw = 0.f;
#pragma unroll
    for (int r = 0; r < N_PER; r++) {
        float4 a = base[r * (D / 4) + tid];
        const float inv = s_inv[r];
        sx = fmaf(a.x, inv, sx);
        sy = fmaf(a.y, inv, sy);
        sz = fmaf(a.z, inv, sz);
        sw = fmaf(a.w, inv, sw);
    }
    float part = sx * sx + sy * sy + sz * sz + sw * sw;

#pragma unroll
    for (int off = 16; off > 0; off >>= 1)
        part += __shfl_down_sync(0xFFFFFFFFu, part, off);

    __shared__ float s_part[8];
    if (lane == 0) s_part[warp] = part;
    __syncthreads();

    if (tid == 0) {
        float ss = 0.0f;
#pragma unroll
        for (int w = 0; w < 8; w++) ss += s_part[w];
        float mean_intra = 1.0f - (ss - (float)N_PER) / (2.0f * N_PAIRS);
        g_group_loss[g] = fmaxf(mean_intra - MARGIN, 0.0f);
        // PDL: signal dependent grid; its wait releases when all CTAs trigger.
        asm volatile("griddepcontrol.launch_dependents;" ::: "memory");
    }
}

// ===== Final reduction, PDL-gated (unchanged from round 10) =====
__global__ __launch_bounds__(512) void final_kernel(float* __restrict__ out) {
    asm volatile("griddepcontrol.wait;" ::: "memory");

    const int tid  = threadIdx.x;
    const int lane = tid & 31;
    const int warp = tid >> 5;

    float acc = 0.0f;
#pragma unroll
    for (int i = tid; i < G; i += 512) acc += __ldcg(&g_group_loss[i]);

#pragma unroll
    for (int off = 16; off > 0; off >>= 1)
        acc += __shfl_xor_sync(0xFFFFFFFFu, acc, off);

    __shared__ float s_part[16];
    if (lane == 0) s_part[warp] = acc;
    __syncthreads();

    if (tid == 0) {
        float s = 0.0f;
#pragma unroll
        for (int w = 0; w < 16; w++) s += s_part[w];
        out[0] = s / (float)G;
    }
}

extern "C" void kernel_launch(void* const* d_in, const int* in_sizes, int n_in,
                              void* d_out, int out_size) {
    const float* emb = (const float*)d_in[0];
    // d_in[1] = labels (arange(B)//8): grouping implicit in block->row mapping
    float* out = (float*)d_out;

    group_kernel<<<G, 256>>>(emb);

    cudaLaunchConfig_t cfg = {};
    cfg.gridDim  = dim3(1, 1, 1);
    cfg.blockDim = dim3(512, 1, 1);
    cfg.dynamicSmemBytes = 0;
    cfg.stream = 0;
    cudaLaunchAttribute attr[1];
    attr[0].id = cudaLaunchAttributeProgrammaticStreamSerialization;
    attr[0].val.programmaticStreamSerializationAllowed = 1;
    cfg.attrs = attr;
    cfg.numAttrs = 1;
    cudaLaunchKernelEx(&cfg, final_kernel, out);
}

// round 16
// speedup vs baseline: 1.1778x; 1.1062x over previous
#include <cuda_runtime.h>
#include <cuda_bf16.h>

#define B     16384
#define D     1024
#define N_PER 8
#define G     (B / N_PER)      // 2048
#define MARGIN 0.5f
#define N_PAIRS 28.0f          // 8*7/2

__device__ float g_group_loss[G];

// ===== Group kernel: round-10 register-held body; phase-1 reduction replaced
// by a multi-value fold (9 shuffles instead of 40). After folds at offsets
// 16/8/4, the partial for row r = (lane>>2)&7 lives in that lane quad; two
// butterfly steps (2,1) finish the sum within the quad. =====
__global__ __launch_bounds__(256) void group_kernel(const float* __restrict__ emb) {
    const int g    = blockIdx.x;
    const int tid  = threadIdx.x;
    const int lane = tid & 31;
    const int warp = tid >> 5;

    const float4* base = reinterpret_cast<const float4*>(emb + (size_t)g * N_PER * D);
    float4 v[N_PER];
    float  sq[N_PER];

#pragma unroll
    for (int r = 0; r < N_PER; r++) {
        v[r] = base[r * (D / 4) + tid];
        float s = v[r].x * v[r].x;
        s = fmaf(v[r].y, v[r].y, s);
        s = fmaf(v[r].z, v[r].z, s);
        s = fmaf(v[r].w, v[r].w, s);
        sq[r] = s;
    }

    // ---- fold 8 -> 4 (offset 16): lo lanes keep rows 0-3, hi keep 4-7 ----
    {
        const bool hi = (lane & 16) != 0;
#pragma unroll
        for (int j = 0; j < 4; j++) {
            float send = hi ? sq[j] : sq[j + 4];
            float recv = __shfl_xor_sync(0xFFFFFFFFu, send, 16);
            sq[j] = (hi ? sq[j + 4] : sq[j]) + recv;
        }
    }
    // ---- fold 4 -> 2 (offset 8) ----
    {
        const bool hi = (lane & 8) != 0;
#pragma unroll
        for (int j = 0; j < 2; j++) {
            float send = hi ? sq[j] : sq[j + 2];
            float recv = __shfl_xor_sync(0xFFFFFFFFu, send, 8);
            sq[j] = (hi ? sq[j + 2] : sq[j]) + recv;
        }
    }
    // ---- fold 2 -> 1 (offset 4) ----
    {
        const bool hi = (lane & 4) != 0;
        float send = hi ? sq[0] : sq[1];
        float recv = __shfl_xor_sync(0xFFFFFFFFu, send, 4);
        sq[0] = (hi ? sq[1] : sq[0]) + recv;
    }
    // ---- finish within the lane quad (offsets 2, 1) ----
    sq[0] += __shfl_xor_sync(0xFFFFFFFFu, sq[0], 2);
    sq[0] += __shfl_xor_sync(0xFFFFFFFFu, sq[0], 1);
    // row index owned by this lane quad
    const int rown = (lane >> 2) & 7;

    __shared__ float s_sq[8][N_PER];
    if ((lane & 3) == 0) s_sq[warp][rown] = sq[0];
    __syncthreads();

    __shared__ float s_inv[N_PER];
    if (tid < N_PER) {
        float s = 0.0f;
#pragma unroll
        for (int w = 0; w < 8; w++) s += s_sq[w][tid];
        float nrm = fmaxf(sqrtf(s), 1e-12f);
        s_inv[tid] = 1.0f / nrm;
    }
    __syncthreads();

    // ---- phase 2: weighted group-sum component + ||s||^2 (unchanged) ----
    float sx = 0.f, sy = 0.f, sz = 0.f, sw = 0.f;
#pragma unroll
    for (int r = 0; r < N_PER; r++) {
        const float inv = s_inv[r];
        sx = fmaf(v[r].x, inv, sx);
        sy = fmaf(v[r].y, inv, sy);
        sz = fmaf(v[r].z, inv, sz);
        sw = fmaf(v[r].w, inv, sw);
    }
    float part = sx * sx + sy * sy + sz * sz + sw * sw;

#pragma unroll
    for (int off = 16; off > 0; off >>= 1)
        part += __shfl_xor_sync(0xFFFFFFFFu, part, off);

    __shared__ float s_part[8];
    if (lane == 0) s_part[warp] = part;
    __syncthreads();

    if (tid == 0) {
        float ss = 0.0f;
#pragma unroll
        for (int w = 0; w < 8; w++) ss += s_part[w];
        float mean_intra = 1.0f - (ss - (float)N_PER) / (2.0f * N_PAIRS);
        g_group_loss[g] = fmaxf(mean_intra - MARGIN, 0.0f);
        // PDL: signal dependent grid; its wait releases when all CTAs trigger.
        asm volatile("griddepcontrol.launch_dependents;" ::: "memory");
    }
}

// ===== Final reduction, PDL-gated (round-10 version, shuffles) =====
__global__ __launch_bounds__(512) void final_kernel(float* __restrict__ out) {
    asm volatile("griddepcontrol.wait;" ::: "memory");

    const int tid  = threadIdx.x;
    const int lane = tid & 31;
    const int warp = tid >> 5;

    float acc = 0.0f;
#pragma unroll
    for (int i = tid; i < G; i += 512) acc += __ldcg(&g_group_loss[i]);

#pragma unroll
    for (int off = 16; off > 0; off >>= 1)
        acc += __shfl_xor_sync(0xFFFFFFFFu, acc, off);

    __shared__ float s_part[16];
    if (lane == 0) s_part[warp] = acc;
    __syncthreads();

    if (tid == 0) {
        float s = 0.0f;
#pragma unroll
        for (int w = 0; w < 16; w++) s += s_part[w];
        out[0] = s / (float)G;
    }
}

extern "C" void kernel_launch(void* const* d_in, const int* in_sizes, int n_in,
                              void* d_out, int out_size) {
    const float* emb = (const float*)d_in[0];
    // d_in[1] = labels (arange(B)//8): grouping implicit in block->row mapping
    float* out = (float*)d_out;

    group_kernel<<<G, 256>>>(emb);

    cudaLaunchConfig_t cfg = {};
    cfg.gridDim  = dim3(1, 1, 1);
    cfg.blockDim = dim3(512, 1, 1);
    cfg.dynamicSmemBytes = 0;
    cfg.stream = 0;
    cudaLaunchAttribute attr[1];
    attr[0].id = cudaLaunchAttributeProgrammaticStreamSerialization;
    attr[0].val.programmaticStreamSerializationAllowed = 1;
    cfg.attrs = attr;
    cfg.numAttrs = 1;
    cudaLaunchKernelEx(&cfg, final_kernel, out);
}